// round 2
// baseline (speedup 1.0000x reference)
#include <cuda_runtime.h>
#include <cstdint>

// ---------------------------------------------------------------------------
// W8A8 Linear: per-tensor int8 quant (x, W) -> int8 GEMM (int32 acc) ->
// dequant * (sx*sw) + bias.  x:[M,K] f32, W:[N,K] f32, bias:[N] f32.
// M=8192, N=2048, K=2048 for this problem (derived from in_sizes).
// ---------------------------------------------------------------------------

#define QMAX 127.0f

// Scratch (allocation-free rule: __device__ globals)
__device__ __align__(16) int8_t g_xq[4 * 2048 * 2048];  // 16 MiB
__device__ __align__(16) int8_t g_wq[2048 * 2048];      //  4 MiB
__device__ unsigned g_amax[2];                          // [0]=x, [1]=w (float bits)

// ---------------------------------------------------------------------------
__global__ void init_amax_kernel() {
    if (threadIdx.x < 2) g_amax[threadIdx.x] = 0u;
}

// Grid-stride abs-max over float4, block-reduce, one atomicMax per block.
__global__ void absmax_kernel(const float* __restrict__ p, int n4, int which) {
    const float4* v = reinterpret_cast<const float4*>(p);
    float m = 0.0f;
    for (int i = blockIdx.x * blockDim.x + threadIdx.x; i < n4;
         i += gridDim.x * blockDim.x) {
        float4 f = v[i];
        m = fmaxf(m, fmaxf(fmaxf(fabsf(f.x), fabsf(f.y)),
                           fmaxf(fabsf(f.z), fabsf(f.w))));
    }
#pragma unroll
    for (int o = 16; o; o >>= 1) m = fmaxf(m, __shfl_xor_sync(0xffffffffu, m, o));
    __shared__ float sm[32];
    int lane = threadIdx.x & 31, w = threadIdx.x >> 5;
    if (lane == 0) sm[w] = m;
    __syncthreads();
    if (w == 0) {
        m = (lane < (int)(blockDim.x >> 5)) ? sm[lane] : 0.0f;
#pragma unroll
        for (int o = 16; o; o >>= 1) m = fmaxf(m, __shfl_xor_sync(0xffffffffu, m, o));
        if (lane == 0) atomicMax(&g_amax[which], __float_as_uint(m));
    }
}

// Quantize: q = clip(rint(t / scale), -128, 127), scale = amax/127 (match jnp).
__global__ void quant_kernel(const float* __restrict__ p, int n4, int which) {
    int8_t* q = which ? g_wq : g_xq;
    float scale = __uint_as_float(g_amax[which]) / QMAX;
    const float4* v = reinterpret_cast<const float4*>(p);
    char4* qv = reinterpret_cast<char4*>(q);
    for (int i = blockIdx.x * blockDim.x + threadIdx.x; i < n4;
         i += gridDim.x * blockDim.x) {
        float4 f = v[i];
        char4 c;
        c.x = (char)(int)fmaxf(-128.0f, fminf(127.0f, rintf(f.x / scale)));
        c.y = (char)(int)fmaxf(-128.0f, fminf(127.0f, rintf(f.y / scale)));
        c.z = (char)(int)fmaxf(-128.0f, fminf(127.0f, rintf(f.z / scale)));
        c.w = (char)(int)fmaxf(-128.0f, fminf(127.0f, rintf(f.w / scale)));
        qv[i] = c;
    }
}

// ---------------------------------------------------------------------------
// int8 GEMM: C[M,N] = Xq[M,K] * Wq[N,K]^T  (both K-major -> row.col mma)
// Block tile 128x128x64, 256 threads (8 warps as 2(M) x 4(N)),
// warp tile 64x32 -> 4x4 grid of m16n8k32 mma per k-step.
// ---------------------------------------------------------------------------
#define BM 128
#define BN 128
#define BK 64
#define BKP 80  // padded smem row stride (bytes): 80/4=20 words -> conflict-free

__device__ __forceinline__ void cp16(void* sdst, const void* gsrc) {
    unsigned saddr = (unsigned)__cvta_generic_to_shared(sdst);
    asm volatile("cp.async.cg.shared.global [%0], [%1], 16;\n" ::
                 "r"(saddr), "l"(gsrc));
}

__device__ __forceinline__ void mma_s8(int* c, const int* a, int b0, int b1) {
    asm volatile(
        "mma.sync.aligned.m16n8k32.row.col.s32.s8.s8.s32 "
        "{%0,%1,%2,%3}, {%4,%5,%6,%7}, {%8,%9}, {%0,%1,%2,%3};\n"
        : "+r"(c[0]), "+r"(c[1]), "+r"(c[2]), "+r"(c[3])
        : "r"(a[0]), "r"(a[1]), "r"(a[2]), "r"(a[3]), "r"(b0), "r"(b1));
}

__global__ __launch_bounds__(256, 2)
void gemm_s8_kernel(const float* __restrict__ bias, float* __restrict__ out,
                    int M, int N, int K) {
    __shared__ int8_t As[2][BM][BKP];
    __shared__ int8_t Bs[2][BN][BKP];

    const int tid  = threadIdx.x;
    const int lane = tid & 31;
    const int wid  = tid >> 5;
    const int warpM = wid >> 2;   // 0..1
    const int warpN = wid & 3;    // 0..3
    const int gid = lane >> 2;    // groupID 0..7
    const int tig = lane & 3;     // thread-in-group 0..3

    const int bm = blockIdx.y * BM;
    const int bn = blockIdx.x * BN;

    int acc[4][4][4];
#pragma unroll
    for (int mt = 0; mt < 4; mt++)
#pragma unroll
        for (int nt = 0; nt < 4; nt++)
#pragma unroll
            for (int r = 0; r < 4; r++) acc[mt][nt][r] = 0;

    // stage loader: 128 rows x 4 x 16B chunks for each of A and B
    auto load_stage = [&](int s, int ko) {
#pragma unroll
        for (int j = 0; j < 2; j++) {
            int ch = tid + 256 * j;
            int r = ch >> 2, cc = ch & 3;
            cp16(&As[s][r][cc * 16], g_xq + (size_t)(bm + r) * K + ko + cc * 16);
            cp16(&Bs[s][r][cc * 16], g_wq + (size_t)(bn + r) * K + ko + cc * 16);
        }
    };

    const int nk = K / BK;  // 32
    load_stage(0, 0);
    asm volatile("cp.async.commit_group;\n");

    const int mbase = warpM * 64;
    const int nbase = warpN * 32;

    for (int kt = 0; kt < nk; kt++) {
        int s = kt & 1;
        if (kt + 1 < nk) load_stage(s ^ 1, (kt + 1) * BK);
        asm volatile("cp.async.commit_group;\n");
        asm volatile("cp.async.wait_group 1;\n");
        __syncthreads();

#pragma unroll
        for (int ks = 0; ks < 2; ks++) {   // two k=32 steps per BK=64
            const int kb = ks * 32;
            int aR[4][4];
#pragma unroll
            for (int mt = 0; mt < 4; mt++) {
                int row = mbase + mt * 16 + gid;
                aR[mt][0] = *(const int*)&As[s][row][kb + tig * 4];
                aR[mt][1] = *(const int*)&As[s][row + 8][kb + tig * 4];
                aR[mt][2] = *(const int*)&As[s][row][kb + 16 + tig * 4];
                aR[mt][3] = *(const int*)&As[s][row + 8][kb + 16 + tig * 4];
            }
#pragma unroll
            for (int nt = 0; nt < 4; nt++) {
                int col = nbase + nt * 8 + gid;
                int b0 = *(const int*)&Bs[s][col][kb + tig * 4];
                int b1 = *(const int*)&Bs[s][col][kb + 16 + tig * 4];
#pragma unroll
                for (int mt = 0; mt < 4; mt++) mma_s8(acc[mt][nt], aR[mt], b0, b1);
            }
        }
        __syncthreads();
    }

    // epilogue: dequant + bias
    const float sx = __uint_as_float(g_amax[0]) / QMAX;
    const float sw = __uint_as_float(g_amax[1]) / QMAX;
    const float sc = sx * sw;

#pragma unroll
    for (int mt = 0; mt < 4; mt++) {
#pragma unroll
        for (int nt = 0; nt < 4; nt++) {
            int row0 = bm + mbase + mt * 16 + gid;
            int col0 = bn + nbase + nt * 8 + tig * 2;
            float bz0 = bias[col0];
            float bz1 = bias[col0 + 1];
            float2 r0, r1;
            r0.x = (float)acc[mt][nt][0] * sc + bz0;
            r0.y = (float)acc[mt][nt][1] * sc + bz1;
            r1.x = (float)acc[mt][nt][2] * sc + bz0;
            r1.y = (float)acc[mt][nt][3] * sc + bz1;
            *reinterpret_cast<float2*>(&out[(size_t)row0 * N + col0]) = r0;
            *reinterpret_cast<float2*>(&out[(size_t)(row0 + 8) * N + col0]) = r1;
        }
    }
}

// ---------------------------------------------------------------------------
extern "C" void kernel_launch(void* const* d_in, const int* in_sizes, int n_in,
                              void* d_out, int out_size) {
    const float* x    = (const float*)d_in[0];
    const float* w    = (const float*)d_in[1];
    const float* bias = (const float*)d_in[2];
    float* out = (float*)d_out;

    const int K = in_sizes[2];           // 2048 (bias length = out features' K? no: K = in dim)
    const int N = in_sizes[1] / K;       // 2048
    const int M = in_sizes[0] / K;       // 8192

    init_amax_kernel<<<1, 32>>>();

    const int n4x = in_sizes[0] / 4;
    const int n4w = in_sizes[1] / 4;
    absmax_kernel<<<1184, 256>>>(x, n4x, 0);
    absmax_kernel<<<1184, 256>>>(w, n4w, 1);
    quant_kernel<<<1184, 256>>>(x, n4x, 0);
    quant_kernel<<<1184, 256>>>(w, n4w, 1);

    dim3 grid(N / BN, M / BM);
    gemm_s8_kernel<<<grid, 256>>>(bias, out, M, N, K);
}